// round 8
// baseline (speedup 1.0000x reference)
#include <cuda_runtime.h>
#include <cuda_fp16.h>
#include <cstdint>

#define D        128
#define NUM_DOW  7
#define NUM_TOD  288
#define NROWS    (NUM_DOW * NUM_TOD)   // 2016
#define RPB      8                     // rows per build block -> 252 blocks
#define TPW      8                     // tokens per warp in gather

// Precomputed output rows for every (dow, tod) pair, fp16: 2016*128*2B = 504 KB.
// Halves the LTS read traffic vs fp32 (the gather is LTS-throughput-bound).
__device__ __align__(16) __half g_table[NROWS * D];

// ---------------------------------------------------------------------------
// Kernel 1: build the 2016-row table (fp32 math, fp16 store).
//   table[row][e] = relu(W1[dow] + W1[7+tod] + b1) dot W2[:, e] + b2[e]
// 252 blocks x 256 threads. Thread = (e = tid&127, half = tid>>7); each
// thread computes 4 rows. ~3.4 warps/SMSP for FFMA-pipe overlap; W2 L2
// traffic = 252 * 64KB = 16 MB.
// ---------------------------------------------------------------------------
__global__ __launch_bounds__(256, 4)
void build_table_kernel(const float* __restrict__ W1,
                        const float* __restrict__ b1,
                        const float* __restrict__ W2,
                        const float* __restrict__ b2) {
    __shared__ __align__(16) float h[RPB][D];

    const int e     = threadIdx.x & (D - 1);   // channel 0..127
    const int half  = threadIdx.x >> 7;        // 0 or 1
    const int rbase = half * (RPB / 2);        // my 4 rows within the block
    const int row0  = blockIdx.x * RPB;

    const float b1e = __ldg(b1 + e);
    #pragma unroll
    for (int i = 0; i < RPB / 2; i++) {
        const int r   = rbase + i;
        const int row = row0 + r;
        const int dow = row / NUM_TOD;
        const int tod = row - dow * NUM_TOD;
        const float v = __ldg(W1 + dow * D + e)
                      + __ldg(W1 + (NUM_DOW + tod) * D + e) + b1e;
        h[r][e] = fmaxf(v, 0.0f);
    }
    __syncthreads();

    float acc[RPB / 2];
    const float b2e = __ldg(b2 + e);
    #pragma unroll
    for (int i = 0; i < RPB / 2; i++) acc[i] = b2e;

    const float4* __restrict__ h4 = (const float4*)&h[0][0];  // [RPB][32]

    #pragma unroll 4
    for (int d4 = 0; d4 < D / 4; d4++) {
        // Same 4 w-values for both halves -> L1 reuse.
        const float w0 = __ldg(W2 + (4 * d4 + 0) * D + e);
        const float w1 = __ldg(W2 + (4 * d4 + 1) * D + e);
        const float w2 = __ldg(W2 + (4 * d4 + 2) * D + e);
        const float w3 = __ldg(W2 + (4 * d4 + 3) * D + e);
        #pragma unroll
        for (int i = 0; i < RPB / 2; i++) {
            const float4 hv = h4[(rbase + i) * (D / 4) + d4];  // LDS.128 bcast
            acc[i] = fmaf(hv.x, w0, acc[i]);
            acc[i] = fmaf(hv.y, w1, acc[i]);
            acc[i] = fmaf(hv.z, w2, acc[i]);
            acc[i] = fmaf(hv.w, w3, acc[i]);
        }
    }

    #pragma unroll
    for (int i = 0; i < RPB / 2; i++)
        g_table[(size_t)(row0 + rbase + i) * D + e] = __float2half(acc[i]);
}

// ---------------------------------------------------------------------------
// Kernel 2: gather, 8 tokens per warp. fp16 table row = 256 B; lane l reads
// 8 B (uint2 = 4 halfs), warp covers the row exactly. 8 independent LDG.64
// (MLP=8 on L2), convert to fp32, 8 STG.128 evict-first (streaming output
// must not evict the 504 KB table from L2). ntok % 8 == 0 (131072).
// ---------------------------------------------------------------------------
__global__ __launch_bounds__(256)
void gather_kernel(const int2* __restrict__ TE,   // [ntok] (dow_raw, tod_raw)
                   float4* __restrict__ out,      // [ntok, 32] float4
                   int ntok) {
    const int warp = (int)((blockIdx.x * blockDim.x + threadIdx.x) >> 5);
    const int lane = threadIdx.x & 31;
    const int t0   = warp * TPW;
    if (t0 >= ntok) return;

    // 8 distinct TE pairs per warp, 4-way broadcast within each address.
    const int2 te = __ldg(TE + t0 + (lane & (TPW - 1)));
    const unsigned myrow =
        ((unsigned)te.x % NUM_DOW) * NUM_TOD + ((unsigned)te.y % NUM_TOD);

    unsigned rows[TPW];
    #pragma unroll
    for (int j = 0; j < TPW; j++)
        rows[j] = __shfl_sync(0xFFFFFFFFu, myrow, j);

    const uint2* __restrict__ tab = (const uint2*)g_table;  // 32 uint2 / row

    uint2 v[TPW];
    #pragma unroll
    for (int j = 0; j < TPW; j++)                 // 8 independent L2 reads
        v[j] = __ldg(tab + (size_t)rows[j] * 32 + lane);

    #pragma unroll
    for (int j = 0; j < TPW; j++) {
        const float2 f01 = __half22float2(*reinterpret_cast<__half2*>(&v[j].x));
        const float2 f23 = __half22float2(*reinterpret_cast<__half2*>(&v[j].y));
        const float4 o = make_float4(f01.x, f01.y, f23.x, f23.y);
        __stcs(out + (size_t)(t0 + j) * (D / 4) + lane, o);  // evict-first
    }
}

// ---------------------------------------------------------------------------
// Inputs (metadata order): TE, T, W1, b1, W2, b2. T unused.
// Output: [B, S, 1, D] float32 — contiguous, identical to [ntok, D].
// ---------------------------------------------------------------------------
extern "C" void kernel_launch(void* const* d_in, const int* in_sizes, int n_in,
                              void* d_out, int out_size) {
    const int2*  TE = (const int2*)d_in[0];
    const float* W1 = (const float*)d_in[2];
    const float* b1 = (const float*)d_in[3];
    const float* W2 = (const float*)d_in[4];
    const float* b2 = (const float*)d_in[5];

    const int ntok = in_sizes[0] / 2;   // B*S = 131072

    build_table_kernel<<<NROWS / RPB, 256>>>(W1, b1, W2, b2);

    // 8 tokens/warp, 8 warps/block -> 64 tokens per block.
    const int nblocks = (ntok + 8 * TPW - 1) / (8 * TPW);
    gather_kernel<<<nblocks, 256>>>(TE, (float4*)d_out, ntok);
}

// round 10
// speedup vs baseline: 1.0250x; 1.0250x over previous
#include <cuda_runtime.h>
#include <cuda_fp16.h>
#include <cstdint>

#define D        128
#define NUM_DOW  7
#define NUM_TOD  288
#define NROWS    (NUM_DOW * NUM_TOD)   // 2016
#define RPB      8                     // rows per build block -> 252 blocks
#define TPW      8                     // tokens per warp in gather
#define TPB      64                    // tokens per gather block (8 warps)
#define ROW_B    (D * 4)               // 512 B output row

// Precomputed output rows for every (dow, tod) pair, fp16: 2016*128*2B = 504 KB.
__device__ __align__(16) __half g_table[NROWS * D];

// ---------------------------------------------------------------------------
// Kernel 1: build the 2016-row table (fp32 math, fp16 store).
//   table[row][e] = relu(W1[dow] + W1[7+tod] + b1) dot W2[:, e] + b2[e]
// 252 blocks x 256 threads; thread = (e, half), 4 rows per thread.
// ---------------------------------------------------------------------------
__global__ __launch_bounds__(256, 4)
void build_table_kernel(const float* __restrict__ W1,
                        const float* __restrict__ b1,
                        const float* __restrict__ W2,
                        const float* __restrict__ b2) {
    __shared__ __align__(16) float h[RPB][D];

    const int e     = threadIdx.x & (D - 1);
    const int half  = threadIdx.x >> 7;
    const int rbase = half * (RPB / 2);
    const int row0  = blockIdx.x * RPB;

    const float b1e = __ldg(b1 + e);
    #pragma unroll
    for (int i = 0; i < RPB / 2; i++) {
        const int r   = rbase + i;
        const int row = row0 + r;
        const int dow = row / NUM_TOD;
        const int tod = row - dow * NUM_TOD;
        const float v = __ldg(W1 + dow * D + e)
                      + __ldg(W1 + (NUM_DOW + tod) * D + e) + b1e;
        h[r][e] = fmaxf(v, 0.0f);
    }
    __syncthreads();

    float acc[RPB / 2];
    const float b2e = __ldg(b2 + e);
    #pragma unroll
    for (int i = 0; i < RPB / 2; i++) acc[i] = b2e;

    const float4* __restrict__ h4 = (const float4*)&h[0][0];  // [RPB][32]

    #pragma unroll 4
    for (int d4 = 0; d4 < D / 4; d4++) {
        const float w0 = __ldg(W2 + (4 * d4 + 0) * D + e);
        const float w1 = __ldg(W2 + (4 * d4 + 1) * D + e);
        const float w2 = __ldg(W2 + (4 * d4 + 2) * D + e);
        const float w3 = __ldg(W2 + (4 * d4 + 3) * D + e);
        #pragma unroll
        for (int i = 0; i < RPB / 2; i++) {
            const float4 hv = h4[(rbase + i) * (D / 4) + d4];
            acc[i] = fmaf(hv.x, w0, acc[i]);
            acc[i] = fmaf(hv.y, w1, acc[i]);
            acc[i] = fmaf(hv.z, w2, acc[i]);
            acc[i] = fmaf(hv.w, w3, acc[i]);
        }
    }

    #pragma unroll
    for (int i = 0; i < RPB / 2; i++)
        g_table[(size_t)(row0 + rbase + i) * D + e] = __float2half(acc[i]);
}

// ---------------------------------------------------------------------------
// Kernel 2: gather with smem staging + one bulk TMA store per block.
//   - warp w handles tokens [blk*64 + w*8, +8): 8 independent fp16 table
//     LDG.64 (MLP=8), convert, STS.128 into a 32 KB smem tile laid out
//     exactly like the output slice.
//   - fence.proxy.async + barrier, then one elected thread issues a single
//     32 KB cp.async.bulk smem -> gmem (block's tokens are contiguous).
// This removes 8 STG.128 per warp (12 cyc LSU each + 4 L1 wavefronts each)
// from the per-thread store path.
// ---------------------------------------------------------------------------
__global__ __launch_bounds__(256)
void gather_kernel(const int2* __restrict__ TE,   // [ntok] (dow_raw, tod_raw)
                   char* __restrict__ out,        // [ntok * 512] bytes
                   int ntok) {
    __shared__ __align__(16) float4 stage[TPB * (D / 4)];   // 32 KB

    const int wid  = threadIdx.x >> 5;
    const int lane = threadIdx.x & 31;
    const int t0   = blockIdx.x * TPB + wid * TPW;

    if (t0 < ntok) {
        // 8 distinct TE pairs per warp (4-way broadcast per address).
        const int2 te = __ldg(TE + t0 + (lane & (TPW - 1)));
        const unsigned myrow =
            ((unsigned)te.x % NUM_DOW) * NUM_TOD + ((unsigned)te.y % NUM_TOD);

        unsigned rows[TPW];
        #pragma unroll
        for (int j = 0; j < TPW; j++)
            rows[j] = __shfl_sync(0xFFFFFFFFu, myrow, j);

        const uint2* __restrict__ tab = (const uint2*)g_table;  // 32 uint2/row

        uint2 v[TPW];
        #pragma unroll
        for (int j = 0; j < TPW; j++)                 // 8 independent L2 reads
            v[j] = __ldg(tab + (size_t)rows[j] * 32 + lane);

        #pragma unroll
        for (int j = 0; j < TPW; j++) {
            const float2 f01 = __half22float2(*reinterpret_cast<__half2*>(&v[j].x));
            const float2 f23 = __half22float2(*reinterpret_cast<__half2*>(&v[j].y));
            // token (wid*8+j), 16B chunk `lane` -> conflict-free STS.128
            stage[(wid * TPW + j) * (D / 4) + lane] =
                make_float4(f01.x, f01.y, f23.x, f23.y);
        }
    }

    // Order generic smem writes before the async-proxy bulk read.
    asm volatile("fence.proxy.async.shared::cta;" ::: "memory");
    __syncthreads();

    if (threadIdx.x == 0) {
        uint32_t s;
        asm("{ .reg .u64 t; cvta.to.shared.u64 t, %1; cvt.u32.u64 %0, t; }"
            : "=r"(s) : "l"(stage));
        char* dst = out + (size_t)blockIdx.x * TPB * ROW_B;
        asm volatile(
            "cp.async.bulk.global.shared::cta.bulk_group [%0], [%1], %2;"
            :: "l"(dst), "r"(s), "r"(TPB * ROW_B) : "memory");
        asm volatile("cp.async.bulk.commit_group;" ::: "memory");
        asm volatile("cp.async.bulk.wait_group.read 0;" ::: "memory");
    }
}

// ---------------------------------------------------------------------------
// Inputs (metadata order): TE, T, W1, b1, W2, b2. T unused.
// Output: [B, S, 1, D] float32 — contiguous, identical to [ntok, D].
// ---------------------------------------------------------------------------
extern "C" void kernel_launch(void* const* d_in, const int* in_sizes, int n_in,
                              void* d_out, int out_size) {
    const int2*  TE = (const int2*)d_in[0];
    const float* W1 = (const float*)d_in[2];
    const float* b1 = (const float*)d_in[3];
    const float* W2 = (const float*)d_in[4];
    const float* b2 = (const float*)d_in[5];

    const int ntok = in_sizes[0] / 2;   // B*S = 131072 (multiple of 64)

    build_table_kernel<<<NROWS / RPB, 256>>>(W1, b1, W2, b2);

    const int nblocks = (ntok + TPB - 1) / TPB;   // 2048
    gather_kernel<<<nblocks, 256>>>(TE, (char*)d_out, ntok);
}